// round 17
// baseline (speedup 1.0000x reference)
#include <cuda_runtime.h>

// CRF Viterbi decode: B=256, T=512, N=128. Output dtype = FLOAT32.
// R17: split-K forward. 256 threads per sequence: thread pair (2j, 2j+1)
// handles destination tag j, each summing 64 of the 128 sources, combined
// with one shfl_xor. Halves per-warp issue AND per-thread dependency chain
// of the serial per-step critical path (which bounds the whole kernel via
// the longest sequence). Backward = R12 core. Content-based input ID.

constexpr int NTAG = 128;
constexpr int TMAX = 512;
constexpr int BMAX = 256;
constexpr int TRS  = 132;   // padded smem row stride (floats) for trT

__device__ float g_hist[(long long)BMAX * TMAX * NTAG];  // 64 MB state history
__device__ int g_perm[3];   // [0]=logits idx, [1]=transitions idx, [2]=seqlen idx

#define ADD_F32X2(out, a, b) \
    asm("add.rn.f32x2 %0, %1, %2;" : "=l"(out) : "l"(a), "l"(b))
#define PACK_F32X2(out, lo, hi) \
    asm("mov.b64 %0, {%1, %2};" : "=l"(out) : "r"(lo), "r"(hi))
#define UNPACK_F32X2(lo, hi, in) \
    asm("mov.b64 {%0, %1}, %2;" : "=r"(lo), "=r"(hi) : "l"(in))

__global__ void classify_kernel(const void* p0, const void* p1, const void* p2)
{
    if (threadIdx.x != 0 || blockIdx.x != 0) return;
    const void* ptrs[3] = {p0, p1, p2};

    int seq_idx = -1;
    float meanabs[3];
    for (int k = 0; k < 3; ++k) {
        const int*   wi = (const int*)ptrs[k];
        const float* wf = (const float*)ptrs[k];
        bool all_len = true;
        float s = 0.0f;
        for (int i = 0; i < 64; ++i) {
            int v = wi[i];
            if (v < 1 || v > TMAX) all_len = false;
            s += fabsf(wf[i]);
        }
        meanabs[k] = s * (1.0f / 64.0f);
        if (all_len && seq_idx < 0) seq_idx = k;
    }
    if (seq_idx < 0) seq_idx = 2;

    int a = -1, c = -1;
    for (int k = 0; k < 3; ++k)
        if (k != seq_idx) { if (a < 0) a = k; else c = k; }

    int tr = (meanabs[a] < meanabs[c]) ? a : c;   // transitions ~10x smaller
    int lg = (tr == a) ? c : a;

    g_perm[0] = lg; g_perm[1] = tr; g_perm[2] = seq_idx;
}

// Monotone order-preserving float->uint (equal floats -> equal uints).
__device__ __forceinline__ unsigned ordered_u32(float f) {
    unsigned u = __float_as_uint(f);
    return ((int)u >= 0) ? (u | 0x80000000u) : ~u;
}

__global__ void __launch_bounds__(256, 2)
crf_fused_kernel(const void* p0, const void* p1, const void* p2,
                 float* __restrict__ out)
{
    const void* ptrs[3] = {p0, p1, p2};
    const float* logits = (const float*)ptrs[g_perm[0]];
    const float* trans  = (const float*)ptrs[g_perm[1]];
    const int*   seqlen = (const int*)ptrs[g_perm[2]];

    extern __shared__ __align__(16) float dsm[];
    float* st    = dsm;             // 2 * NTAG state double buffer
    float* sm_tr = dsm + 2 * NTAG;  // sm_tr[j*TRS+i] = trans[i][j]

    const int tid = threadIdx.x;
    const int j = tid >> 1;         // destination tag
    const int h = tid & 1;          // source half: [64h, 64h+64)
    const int b = blockIdx.x;

    // This thread's 64 transition values trans[64h + n][j], packed f32x2.
    // Also build the transposed smem table for the backward pass.
    unsigned long long trp[32];
#pragma unroll
    for (int m = 0; m < 32; ++m) {
        const int src = 64 * h + 2 * m;
        unsigned int lo = __float_as_uint(trans[src * NTAG + j]);
        unsigned int hi = __float_as_uint(trans[(src + 1) * NTAG + j]);
        PACK_F32X2(trp[m], lo, hi);
        *(float2*)(sm_tr + j * TRS + 64 * h + 2 * m) =
            make_float2(__uint_as_float(lo), __uint_as_float(hi));
    }

    const float* lg = logits + (long long)b * TMAX * NTAG;
    float* hist = g_hist + (long long)b * TMAX * NTAG;

    int L = seqlen[b];
    if (L < 1) L = 1;
    if (L > TMAX) L = TMAX;

    if (h == 0) {
        float s0 = lg[j];
        st[j] = s0;
        hist[j] = s0;
    }
    __syncthreads();

    // ---- Forward: split-K max-only. Each thread: 64 sources, 8 chains. ----
    for (int t = 1; t < L; ++t) {
        const float x = lg[t * NTAG + j];
        const ulonglong2* s2 =
            (const ulonglong2*)(st + ((t - 1) & 1) * NTAG) + h * 16;

        float best[8];
#pragma unroll
        for (int k = 0; k < 8; ++k) best[k] = -3.402823466e38f;

#pragma unroll
        for (int k = 0; k < 8; ++k) {
#pragma unroll
            for (int q = 0; q < 2; ++q) {
                ulonglong2 u = s2[k * 2 + q];
                unsigned long long r0, r1;
                ADD_F32X2(r0, u.x, trp[k * 4 + q * 2]);
                ADD_F32X2(r1, u.y, trp[k * 4 + q * 2 + 1]);
                unsigned int a0, a1, b0, b1;
                UNPACK_F32X2(a0, a1, r0);
                UNPACK_F32X2(b0, b1, r1);
                best[k] = fmaxf(best[k], __uint_as_float(a0));
                best[k] = fmaxf(best[k], __uint_as_float(a1));
                best[k] = fmaxf(best[k], __uint_as_float(b0));
                best[k] = fmaxf(best[k], __uint_as_float(b1));
            }
        }

        float m0 = fmaxf(best[0], best[1]);
        float m1 = fmaxf(best[2], best[3]);
        float m2 = fmaxf(best[4], best[5]);
        float m3 = fmaxf(best[6], best[7]);
        float bb = fmaxf(fmaxf(m0, m1), fmaxf(m2, m3));

        // Combine the two halves of this destination tag.
        float other = __shfl_xor_sync(0xFFFFFFFFu, bb, 1);
        float full = fmaxf(bb, other);

        if (h == 0) {
            float nv = full + x;
            st[(t & 1) * NTAG + j] = nv;
            hist[t * NTAG + j] = nv;
        }
        __syncthreads();
    }

    // Zero masked tail [L, T) — float output, d_out poisoned.
    float* orow = out + b * TMAX;
    for (int p = L + tid; p < TMAX; p += 2 * NTAG)
        orow[p] = 0.0f;

    // ---- Backward: warp 0 backtraces this sequence (R12 core) ----
    if (tid < 32) {
        const int lane = tid;
        const int i0 = lane * 4;
        const float* fs = st + ((L - 1) & 1) * NTAG;
        int cur;

        auto wargmax = [&](float v0, float v1, float v2, float v3) -> int {
            float best = v0; int lidx = 0; bool p;
            p = v1 > best; best = p ? v1 : best; lidx = p ? 1 : lidx;
            p = v2 > best; best = p ? v2 : best; lidx = p ? 2 : lidx;
            p = v3 > best; best = p ? v3 : best; lidx = p ? 3 : lidx;
            unsigned ub = ordered_u32(best);
            unsigned wm = __reduce_max_sync(0xFFFFFFFFu, ub);
            unsigned gi = (ub == wm) ? (unsigned)(i0 + lidx) : 0xFFFFFFFFu;
            return (int)__reduce_min_sync(0xFFFFFFFFu, gi);
        };

        {
            float4 hh = *(const float4*)(fs + i0);
            cur = wargmax(hh.x, hh.y, hh.z, hh.w);
            if (lane == 0) orow[L - 1] = (float)cur;
        }

        auto step = [&](float4 hh, int tt) {
            float4 tv = *(const float4*)(sm_tr + cur * TRS + i0);
            cur = wargmax(hh.x + tv.x, hh.y + tv.y, hh.z + tv.z, hh.w + tv.w);
            if (lane == 0) orow[tt - 1] = (float)cur;
        };

        float4 bufA[8], bufB[8];
        auto load8 = [&](float4 (&buf)[8], int tb) {
#pragma unroll
            for (int k = 0; k < 8; ++k) {
                int rr = tb - 1 - k;
                rr = (rr >= 0) ? rr : 0;
                buf[k] = *(const float4*)(hist + rr * NTAG + i0);
            }
        };

        int t = L - 1;
        if (t >= 1) {
            load8(bufA, t);
            while (true) {
                load8(bufB, t - 8);
#pragma unroll
                for (int k = 0; k < 8; ++k)
                    if (t - k >= 1) step(bufA[k], t - k);
                t -= 8;
                if (t < 1) break;

                load8(bufA, t - 8);
#pragma unroll
                for (int k = 0; k < 8; ++k)
                    if (t - k >= 1) step(bufB[k], t - k);
                t -= 8;
                if (t < 1) break;
            }
        }
    }
}

extern "C" void kernel_launch(void* const* d_in, const int* in_sizes, int n_in,
                              void* d_out, int out_size) {
    (void)in_sizes; (void)out_size;
    const void* p0 = d_in[0];
    const void* p1 = (n_in > 1) ? d_in[1] : d_in[0];
    const void* p2 = (n_in > 2) ? d_in[2] : d_in[0];
    float* out = (float*)d_out;

    const int smem_bytes = (2 * NTAG + NTAG * TRS) * 4;   // 68608
    cudaFuncSetAttribute(crf_fused_kernel,
                         cudaFuncAttributeMaxDynamicSharedMemorySize, smem_bytes);

    classify_kernel<<<1, 1>>>(p0, p1, p2);
    crf_fused_kernel<<<BMAX, 2 * NTAG, smem_bytes>>>(p0, p1, p2, out);
}